// round 1
// baseline (speedup 1.0000x reference)
#include <cuda_runtime.h>

#define BSZ 16
#define SSZ 4096
#define HSZ 1024
#define NTOK (BSZ * SSZ)

// Scratch (no allocations allowed): scores and probs for all tokens.
__device__ float g_scores[NTOK];
__device__ float g_probs[NTOK];

// ---------------------------------------------------------------------------
// Kernel A: fused scores GEMM.
// scores[t] = sum_o tanh( dot(x[t,:], W[o,:]) + b[o] ) * key[o]
// Block tile: 64 tokens x 64 outputs, looped over all 1024 outputs.
// 256 threads, 4x4 microtile, K-chunk 16. Never materializes `query`.
// ---------------------------------------------------------------------------
__global__ __launch_bounds__(256) void scores_kernel(
    const float* __restrict__ x, const float* __restrict__ W,
    const float* __restrict__ bias, const float* __restrict__ key)
{
    __shared__ float xs[16][64];
    __shared__ float ws[16][64];
    __shared__ float s_key[HSZ];
    __shared__ float s_bias[HSZ];

    const int tid = threadIdx.x;
    for (int i = tid; i < HSZ; i += 256) {
        s_key[i]  = key[i];
        s_bias[i] = bias[i];
    }

    const int t0 = blockIdx.x * 64;          // first token of this block
    const int ty = tid >> 4;                 // 0..15 (token group)
    const int tx = tid & 15;                 // 0..15 (output group)
    const int mload = tid >> 2;              // 0..63 (row for global loads)
    const int kload = (tid & 3) << 2;        // 0,4,8,12 (k offset, float4)

    float sc[4] = {0.f, 0.f, 0.f, 0.f};     // per-thread score partials (4 tokens)

    __syncthreads();

    for (int n0 = 0; n0 < HSZ; n0 += 64) {
        float acc[4][4];
        #pragma unroll
        for (int i = 0; i < 4; i++)
            #pragma unroll
            for (int j = 0; j < 4; j++) acc[i][j] = 0.f;

        for (int k0 = 0; k0 < HSZ; k0 += 16) {
            // Stage x tile [64 tok x 16 k] and W tile [64 out x 16 k], transposed.
            float4 xv = *(const float4*)(x + (size_t)(t0 + mload) * HSZ + k0 + kload);
            float4 wv = *(const float4*)(W + (size_t)(n0 + mload) * HSZ + k0 + kload);
            xs[kload + 0][mload] = xv.x;
            xs[kload + 1][mload] = xv.y;
            xs[kload + 2][mload] = xv.z;
            xs[kload + 3][mload] = xv.w;
            ws[kload + 0][mload] = wv.x;
            ws[kload + 1][mload] = wv.y;
            ws[kload + 2][mload] = wv.z;
            ws[kload + 3][mload] = wv.w;
            __syncthreads();

            #pragma unroll
            for (int kk = 0; kk < 16; kk++) {
                float4 av = *(const float4*)&xs[kk][ty << 2];
                float4 bv = *(const float4*)&ws[kk][tx << 2];
                float a[4] = {av.x, av.y, av.z, av.w};
                float b4[4] = {bv.x, bv.y, bv.z, bv.w};
                #pragma unroll
                for (int i = 0; i < 4; i++)
                    #pragma unroll
                    for (int j = 0; j < 4; j++)
                        acc[i][j] += a[i] * b4[j];
            }
            __syncthreads();
        }

        // Epilogue for this output tile: tanh, key-weight, fold into score.
        #pragma unroll
        for (int j = 0; j < 4; j++) {
            int o = n0 + (tx << 2) + j;
            float kb = s_key[o];
            float bb = s_bias[o];
            #pragma unroll
            for (int i = 0; i < 4; i++)
                sc[i] += tanhf(acc[i][j] + bb) * kb;
        }
    }

    // Reduce over the 16 tx lanes (contiguous half-warp per ty).
    #pragma unroll
    for (int i = 0; i < 4; i++) {
        float v = sc[i];
        v += __shfl_xor_sync(0xffffffffu, v, 1, 16);
        v += __shfl_xor_sync(0xffffffffu, v, 2, 16);
        v += __shfl_xor_sync(0xffffffffu, v, 4, 16);
        v += __shfl_xor_sync(0xffffffffu, v, 8, 16);
        sc[i] = v;
    }
    if (tx == 0) {
        #pragma unroll
        for (int i = 0; i < 4; i++)
            g_scores[t0 + (ty << 2) + i] = sc[i];
    }
}

// ---------------------------------------------------------------------------
// Kernel B1: per-batch masked softmax over scores -> probs (0 beyond length).
// ---------------------------------------------------------------------------
__global__ __launch_bounds__(256) void softmax_kernel(const int* __restrict__ lengths)
{
    __shared__ float red[256];
    const int b = blockIdx.x;
    const int len = lengths[b];
    const float* sc = g_scores + b * SSZ;
    const int tid = threadIdx.x;

    float m = -1e30f;
    for (int s = tid; s < len; s += 256) m = fmaxf(m, sc[s]);
    red[tid] = m;
    __syncthreads();
    for (int o = 128; o > 0; o >>= 1) {
        if (tid < o) red[tid] = fmaxf(red[tid], red[tid + o]);
        __syncthreads();
    }
    m = red[0];
    __syncthreads();

    float sum = 0.f;
    for (int s = tid; s < len; s += 256) sum += expf(sc[s] - m);
    red[tid] = sum;
    __syncthreads();
    for (int o = 128; o > 0; o >>= 1) {
        if (tid < o) red[tid] += red[tid + o];
        __syncthreads();
    }
    const float inv = 1.0f / red[0];

    for (int s = tid; s < SSZ; s += 256)
        g_probs[b * SSZ + s] = (s < len) ? expf(sc[s] - m) * inv : 0.f;
}

// ---------------------------------------------------------------------------
// Kernel B2: out[b,h] = sum_{s<len} probs[b,s] * x[b,s,h]
// Grid: (H/128, B). Coalesced over h, 4-deep s-unroll for MLP.
// ---------------------------------------------------------------------------
__global__ __launch_bounds__(128) void output_kernel(
    const float* __restrict__ x, const int* __restrict__ lengths,
    float* __restrict__ out)
{
    const int b = blockIdx.y;
    const int h = blockIdx.x * 128 + threadIdx.x;
    const int len = lengths[b];
    const float* xb = x + (size_t)b * SSZ * HSZ + h;
    const float* pb = g_probs + b * SSZ;

    float a0 = 0.f, a1 = 0.f, a2 = 0.f, a3 = 0.f;
    int s = 0;
    for (; s + 4 <= len; s += 4) {
        a0 += pb[s + 0] * xb[(size_t)(s + 0) * HSZ];
        a1 += pb[s + 1] * xb[(size_t)(s + 1) * HSZ];
        a2 += pb[s + 2] * xb[(size_t)(s + 2) * HSZ];
        a3 += pb[s + 3] * xb[(size_t)(s + 3) * HSZ];
    }
    for (; s < len; s++) a0 += pb[s] * xb[(size_t)s * HSZ];

    out[b * HSZ + h] = (a0 + a1) + (a2 + a3);
}

// ---------------------------------------------------------------------------
extern "C" void kernel_launch(void* const* d_in, const int* in_sizes, int n_in,
                              void* d_out, int out_size)
{
    const float* x       = (const float*)d_in[0];
    const int*   lengths = (const int*)  d_in[1];
    const float* W       = (const float*)d_in[2];
    const float* bias    = (const float*)d_in[3];
    const float* key     = (const float*)d_in[4];
    float* out = (float*)d_out;

    scores_kernel<<<NTOK / 64, 256>>>(x, W, bias, key);
    softmax_kernel<<<BSZ, 256>>>(lengths);
    output_kernel<<<dim3(HSZ / 128, BSZ), 128>>>(x, lengths, out);
}

// round 4
// speedup vs baseline: 2.3985x; 2.3985x over previous
#include <cuda_runtime.h>
#include <cuda_bf16.h>
#include <cstdint>

#define BSZ 16
#define SSZ 4096
#define HSZ 1024
#define NTOK (BSZ * SSZ)

#define M_CTA 128
#define N_CHUNK 256
#define NCHUNK (HSZ / N_CHUNK)   // 4
#define BK 32
#define NKSTAGE (HSZ / BK)       // 32 stages per n-chunk
#define PITCH 80                 // bytes per 32-elem bf16 row (64B data + 16B skew)

// dynamic smem layout (bytes)
#define SOFF_SCORE 0             // float[128]
#define SOFF_KEY   512           // float[1024]
#define SOFF_BIAS  4608          // float[1024]
#define SOFF_STAGE 8704
#define AHI 0
#define ALO (128 * PITCH)        // 10240
#define BHI (2 * 128 * PITCH)    // 20480
#define BLO (BHI + 256 * PITCH)  // 40960
#define STAGE_BYTES (BLO + 256 * PITCH)  // 61440
#define SMEM_TOTAL (SOFF_STAGE + 2 * STAGE_BYTES)  // 131584

// ---- scratch (no allocations allowed) ----
__device__ float g_scores[NTOK];
__device__ float g_probs[NTOK];
__device__ __nv_bfloat16 g_xh[(size_t)NTOK * HSZ];
__device__ __nv_bfloat16 g_xl[(size_t)NTOK * HSZ];
__device__ __nv_bfloat16 g_wh[(size_t)HSZ * HSZ];
__device__ __nv_bfloat16 g_wl[(size_t)HSZ * HSZ];

// ---------------------------------------------------------------------------
__device__ __forceinline__ uint32_t s2u(const void* p) {
    return (uint32_t)__cvta_generic_to_shared(p);
}

__device__ __forceinline__ void cp16(uint32_t saddr, const void* gptr) {
    asm volatile("cp.async.cg.shared.global [%0], [%1], 16;"
                 :: "r"(saddr), "l"(gptr) : "memory");
}

#define LDMX4(r0, r1, r2, r3, addr) \
    asm volatile("ldmatrix.sync.aligned.m8n8.x4.shared.b16 {%0,%1,%2,%3}, [%4];" \
                 : "=r"(r0), "=r"(r1), "=r"(r2), "=r"(r3) : "r"(addr))

#define MMA16816(d, a, b) \
    asm volatile("mma.sync.aligned.m16n8k16.row.col.f32.bf16.bf16.f32 " \
                 "{%0,%1,%2,%3}, {%4,%5,%6,%7}, {%8,%9}, {%0,%1,%2,%3};" \
                 : "+f"((d)[0]), "+f"((d)[1]), "+f"((d)[2]), "+f"((d)[3]) \
                 : "r"((a)[0]), "r"((a)[1]), "r"((a)[2]), "r"((a)[3]), \
                   "r"((b)[0]), "r"((b)[1]))

__device__ __forceinline__ float ftanh(float v) {
    float e = __expf(2.0f * v);
    return 1.0f - 2.0f / (e + 1.0f);
}

// ---------------------------------------------------------------------------
// Kernel 0: fp32 -> bf16 hi/lo split
// ---------------------------------------------------------------------------
__global__ __launch_bounds__(256) void convert_kernel(
    const float* __restrict__ src, __nv_bfloat16* __restrict__ hi,
    __nv_bfloat16* __restrict__ lo, size_t n)
{
    size_t i = ((size_t)blockIdx.x * blockDim.x + threadIdx.x) * 4;
    if (i >= n) return;
    float4 v = *(const float4*)(src + i);
    float a[4] = {v.x, v.y, v.z, v.w};
    __nv_bfloat16 h[4], l[4];
    #pragma unroll
    for (int j = 0; j < 4; j++) {
        h[j] = __float2bfloat16(a[j]);
        l[j] = __float2bfloat16(a[j] - __bfloat162float(h[j]));
    }
    ((__nv_bfloat162*)(hi + i))[0] = __halves2bfloat162(h[0], h[1]);
    ((__nv_bfloat162*)(hi + i))[1] = __halves2bfloat162(h[2], h[3]);
    ((__nv_bfloat162*)(lo + i))[0] = __halves2bfloat162(l[0], l[1]);
    ((__nv_bfloat162*)(lo + i))[1] = __halves2bfloat162(l[2], l[3]);
}

// ---------------------------------------------------------------------------
// Stage loader: A (128 x 32 bf16, hi+lo) + B (256 x 32 bf16, hi+lo).
// Row pitch 80B: 16B chunk c of row r sits at 80r+16c -> bank group (5r+c)&7,
// distinct for any 8 consecutive rows at fixed c (conflict-free ldmatrix).
// ---------------------------------------------------------------------------
__device__ __forceinline__ void load_stage(uint32_t sb, int t0, int n0, int k0, int tid)
{
    {   // A: 128 rows x 4 chunks = 512 slots, one per thread
        int r = tid >> 2, c = tid & 3;
        uint32_t so = (uint32_t)(r * PITCH + c * 16);
        size_t gi = (size_t)(t0 + r) * HSZ + k0 + c * 8;
        cp16(sb + AHI + so, g_xh + gi);
        cp16(sb + ALO + so, g_xl + gi);
    }
    #pragma unroll
    for (int it = 0; it < 2; it++) {   // B: 256 rows x 4 chunks = 1024 slots
        int idx = tid + it * 512;
        int r = idx >> 2, c = idx & 3;
        uint32_t so = (uint32_t)(r * PITCH + c * 16);
        size_t gi = (size_t)(n0 + r) * HSZ + k0 + c * 8;
        cp16(sb + BHI + so, g_wh + gi);
        cp16(sb + BLO + so, g_wl + gi);
    }
    asm volatile("cp.async.commit_group;" ::: "memory");
}

// ---------------------------------------------------------------------------
// Kernel A: fused scores GEMM, bf16x3 split precision on mma.sync HMMA.
// scores[t] = sum_o tanh( dot(x[t,:], W[o,:]) + b[o] ) * key[o]
// ---------------------------------------------------------------------------
__global__ void __launch_bounds__(512, 1) gemm_scores_kernel(
    const float* __restrict__ bias, const float* __restrict__ key)
{
    extern __shared__ char smem[];
    const uint32_t sbase = s2u(smem);
    const int tid = threadIdx.x;
    const int wid = tid >> 5;
    const int lid = tid & 31;
    const int wm  = wid & 3;          // warp m index (4)
    const int wn  = wid >> 2;         // warp n index (4)
    const int t0  = blockIdx.x * M_CTA;

    float* s_score = (float*)(smem + SOFF_SCORE);
    float* s_key   = (float*)(smem + SOFF_KEY);
    float* s_bias  = (float*)(smem + SOFF_BIAS);
    for (int i = tid; i < HSZ; i += 512) {
        s_key[i]  = key[i];
        s_bias[i] = bias[i];
    }
    if (tid < M_CTA) s_score[tid] = 0.0f;

    // ldmatrix lane geometry
    const int g  = lid >> 3;          // quad-group 0..3
    const int r8 = lid & 7;
    const int a_row  = wm * 32 + (g & 1) * 8 + r8;   // + i*16
    const int a_kh   = g >> 1;                       // k8-half
    const int b_rowb = wn * 64 + (g >> 1) * 8 + r8;  // + nh*32 + p*16
    const int b_kh   = g & 1;

    float score_p[2][2];              // per-thread row partials [i][mhalf]

    for (int nc = 0; nc < NCHUNK; nc++) {
        const int n0 = nc * N_CHUNK;
        float acc[2][8][4];
        #pragma unroll
        for (int i = 0; i < 2; i++)
            #pragma unroll
            for (int j = 0; j < 8; j++)
                #pragma unroll
                for (int c = 0; c < 4; c++) acc[i][j][c] = 0.0f;

        __syncthreads();              // protect buf0 from previous chunk readers
        load_stage(sbase + SOFF_STAGE, t0, n0, 0, tid);

        for (int ks = 0; ks < NKSTAGE; ks++) {
            const uint32_t stg = sbase + SOFF_STAGE + (uint32_t)(ks & 1) * STAGE_BYTES;
            if (ks + 1 < NKSTAGE) {
                load_stage(sbase + SOFF_STAGE + (uint32_t)((ks + 1) & 1) * STAGE_BYTES,
                           t0, n0, (ks + 1) * BK, tid);
                asm volatile("cp.async.wait_group 1;" ::: "memory");
            } else {
                asm volatile("cp.async.wait_group 0;" ::: "memory");
            }
            __syncthreads();

            #pragma unroll
            for (int k16 = 0; k16 < 2; k16++) {
                uint32_t ah[2][4], al[2][4];
                #pragma unroll
                for (int i = 0; i < 2; i++) {
                    uint32_t off = (uint32_t)((a_row + i * 16) * PITCH
                                            + 16 * (k16 * 2 + a_kh));
                    LDMX4(ah[i][0], ah[i][1], ah[i][2], ah[i][3], stg + AHI + off);
                    LDMX4(al[i][0], al[i][1], al[i][2], al[i][3], stg + ALO + off);
                }
                #pragma unroll
                for (int nh = 0; nh < 2; nh++) {
                    uint32_t bh[4][2], bl[4][2];
                    #pragma unroll
                    for (int p = 0; p < 2; p++) {
                        uint32_t off = (uint32_t)((b_rowb + nh * 32 + p * 16) * PITCH
                                                + 16 * (k16 * 2 + b_kh));
                        LDMX4(bh[2*p][0], bh[2*p][1], bh[2*p+1][0], bh[2*p+1][1],
                              stg + BHI + off);
                        LDMX4(bl[2*p][0], bl[2*p][1], bl[2*p+1][0], bl[2*p+1][1],
                              stg + BLO + off);
                    }
                    #pragma unroll
                    for (int i = 0; i < 2; i++)
                        #pragma unroll
                        for (int j = 0; j < 4; j++) {
                            MMA16816(acc[i][nh * 4 + j], ah[i], bh[j]);  // hi*hi
                            MMA16816(acc[i][nh * 4 + j], ah[i], bl[j]);  // hi*lo
                            MMA16816(acc[i][nh * 4 + j], al[i], bh[j]);  // lo*hi
                        }
                }
            }
            __syncthreads();
        }

        // epilogue: tanh(acc + bias) * key, reduce over n into s_score
        #pragma unroll
        for (int i = 0; i < 2; i++)
            #pragma unroll
            for (int mh = 0; mh < 2; mh++) score_p[i][mh] = 0.0f;

        #pragma unroll
        for (int i = 0; i < 2; i++)
            #pragma unroll
            for (int j = 0; j < 8; j++)
                #pragma unroll
                for (int c = 0; c < 4; c++) {
                    int n = n0 + wn * 64 + j * 8 + (lid & 3) * 2 + (c & 1);
                    float v = ftanh(acc[i][j][c] + s_bias[n]) * s_key[n];
                    score_p[i][c >> 1] += v;
                }

        #pragma unroll
        for (int i = 0; i < 2; i++)
            #pragma unroll
            for (int mh = 0; mh < 2; mh++) {
                float v = score_p[i][mh];
                v += __shfl_xor_sync(0xffffffffu, v, 1);
                v += __shfl_xor_sync(0xffffffffu, v, 2);
                if ((lid & 3) == 0) {
                    int m = wm * 32 + i * 16 + mh * 8 + (lid >> 2);
                    atomicAdd(&s_score[m], v);
                }
            }
    }

    __syncthreads();
    if (tid < M_CTA) g_scores[t0 + tid] = s_score[tid];
}

// ---------------------------------------------------------------------------
// Kernel B1: per-batch masked softmax over scores -> probs (0 beyond length).
// ---------------------------------------------------------------------------
__global__ __launch_bounds__(256) void softmax_kernel(const int* __restrict__ lengths)
{
    __shared__ float red[256];
    const int b = blockIdx.x;
    const int len = lengths[b];
    const float* sc = g_scores + b * SSZ;
    const int tid = threadIdx.x;

    float m = -1e30f;
    for (int s = tid; s < len; s += 256) m = fmaxf(m, sc[s]);
    red[tid] = m;
    __syncthreads();
    for (int o = 128; o > 0; o >>= 1) {
        if (tid < o) red[tid] = fmaxf(red[tid], red[tid + o]);
        __syncthreads();
    }
    m = red[0];
    __syncthreads();

    float sum = 0.f;
    for (int s = tid; s < len; s += 256) sum += expf(sc[s] - m);
    red[tid] = sum;
    __syncthreads();
    for (int o = 128; o > 0; o >>= 1) {
        if (tid < o) red[tid] += red[tid + o];
        __syncthreads();
    }
    const float inv = 1.0f / red[0];

    for (int s = tid; s < SSZ; s += 256)
        g_probs[b * SSZ + s] = (s < len) ? expf(sc[s] - m) * inv : 0.f;
}

// ---------------------------------------------------------------------------
// Kernel B2: out[b,h] = sum_{s<len} probs[b,s] * x[b,s,h]
// ---------------------------------------------------------------------------
__global__ __launch_bounds__(128) void output_kernel(
    const float* __restrict__ x, const int* __restrict__ lengths,
    float* __restrict__ out)
{
    const int b = blockIdx.y;
    const int h = blockIdx.x * 128 + threadIdx.x;
    const int len = lengths[b];
    const float* xb = x + (size_t)b * SSZ * HSZ + h;
    const float* pb = g_probs + b * SSZ;

    float a0 = 0.f, a1 = 0.f, a2 = 0.f, a3 = 0.f;
    int s = 0;
    for (; s + 4 <= len; s += 4) {
        a0 += pb[s + 0] * xb[(size_t)(s + 0) * HSZ];
        a1 += pb[s + 1] * xb[(size_t)(s + 1) * HSZ];
        a2 += pb[s + 2] * xb[(size_t)(s + 2) * HSZ];
        a3 += pb[s + 3] * xb[(size_t)(s + 3) * HSZ];
    }
    for (; s < len; s++) a0 += pb[s] * xb[(size_t)s * HSZ];

    out[b * HSZ + h] = (a0 + a1) + (a2 + a3);
}

// ---------------------------------------------------------------------------
extern "C" void kernel_launch(void* const* d_in, const int* in_sizes, int n_in,
                              void* d_out, int out_size)
{
    const float* x       = (const float*)d_in[0];
    const int*   lengths = (const int*)  d_in[1];
    const float* W       = (const float*)d_in[2];
    const float* bias    = (const float*)d_in[3];
    const float* key     = (const float*)d_in[4];
    float* out = (float*)d_out;

    cudaFuncSetAttribute(gemm_scores_kernel,
                         cudaFuncAttributeMaxDynamicSharedMemorySize, SMEM_TOTAL);

    __nv_bfloat16 *xh, *xl, *wh, *wl;
    cudaGetSymbolAddress((void**)&xh, g_xh);
    cudaGetSymbolAddress((void**)&xl, g_xl);
    cudaGetSymbolAddress((void**)&wh, g_wh);
    cudaGetSymbolAddress((void**)&wl, g_wl);

    size_t nx = (size_t)NTOK * HSZ;
    size_t nw = (size_t)HSZ * HSZ;
    convert_kernel<<<(unsigned)(nx / (256 * 4)), 256>>>(x, xh, xl, nx);
    convert_kernel<<<(unsigned)(nw / (256 * 4)), 256>>>(W, wh, wl, nw);

    gemm_scores_kernel<<<NTOK / M_CTA, 512, SMEM_TOTAL>>>(bias, key);
    softmax_kernel<<<BSZ, 256>>>(lengths);
    output_kernel<<<dim3(HSZ / 128, BSZ), 128>>>(x, lengths, out);
}